// round 1
// baseline (speedup 1.0000x reference)
#include <cuda_runtime.h>
#include <math.h>

#define BATCH 32
#define CH    512
#define NTOK  1024   // H*W
#define NGRP  32
#define CPG   16     // CH / NGRP

// -------- scratch (device globals; no runtime allocation) --------
__device__ float g_h[(size_t)BATCH * CH * NTOK];
__device__ float g_q[(size_t)BATCH * CH * NTOK];
__device__ float g_k[(size_t)BATCH * CH * NTOK];
__device__ float g_v[(size_t)BATCH * CH * NTOK];
__device__ float g_s[(size_t)BATCH * NTOK * NTOK];
__device__ float g_o[(size_t)BATCH * CH * NTOK];

// -------- GroupNorm: one block per (batch, group) --------
__global__ void gn_kernel(const float* __restrict__ x,
                          const float* __restrict__ gw,
                          const float* __restrict__ gb,
                          float* __restrict__ h) {
    const int bg = blockIdx.x;           // b*NGRP + g
    const int g  = bg % NGRP;
    const int n  = CPG * NTOK;           // 16384 elems per (b,g)
    const size_t base = (size_t)bg * n;
    const int t = threadIdx.x;

    float s = 0.f, ss = 0.f;
    for (int i = t; i < n; i += 256) {
        float v = x[base + i];
        s += v; ss += v * v;
    }
    __shared__ float rs[256], rq[256];
    rs[t] = s; rq[t] = ss;
    __syncthreads();
    for (int o = 128; o > 0; o >>= 1) {
        if (t < o) { rs[t] += rs[t + o]; rq[t] += rq[t + o]; }
        __syncthreads();
    }
    const float mean = rs[0] * (1.0f / n);
    const float var  = rq[0] * (1.0f / n) - mean * mean;
    const float rstd = rsqrtf(var + 1e-5f);

    for (int i = t; i < n; i += 256) {
        int ch = g * CPG + (i >> 10);    // i / NTOK
        h[base + i] = (x[base + i] - mean) * rstd * gw[ch] + gb[ch];
    }
}

// -------- batched SGEMM: C[m,n] = alpha * sum_k A(m,k)*B(k,n) (+bias[m]) (+resid) --------
// TA: A stored [K, M] (transposed access). TB: B stored [N, K].
// BM=BN=128, BK=8, 256 threads, 8x8 per thread. All dims multiples of tiles.
template<bool TA, bool TB>
__global__ void __launch_bounds__(256)
gemm_kernel(const float* __restrict__ A, const float* __restrict__ Bm,
            float* __restrict__ Cm,
            int M, int N, int K, int lda, int ldb, int ldc,
            long strideA, long strideB, long strideC,
            float alpha, const float* __restrict__ bias,
            const float* __restrict__ resid, long strideR) {
    const int BM = 128, BN = 128, BK = 8;
    __shared__ float As[BK][BM];
    __shared__ float Bs[BK][BN];

    const int b  = blockIdx.z;
    const float* Ab = A  + (size_t)b * strideA;
    const float* Bb = Bm + (size_t)b * strideB;
    float*       Cb = Cm + (size_t)b * strideC;

    const int m0 = blockIdx.y * BM;
    const int n0 = blockIdx.x * BN;
    const int t  = threadIdx.x;
    const int tm = (t >> 4) << 3;   // (t/16)*8
    const int tn = (t & 15) << 3;   // (t%16)*8

    float acc[8][8] = {};

    for (int k0 = 0; k0 < K; k0 += BK) {
        #pragma unroll
        for (int i = 0; i < 4; i++) {
            int e = t + 256 * i;
            if (TA) {
                int mm = e & 127, kk = e >> 7;
                As[kk][mm] = Ab[(size_t)(k0 + kk) * lda + m0 + mm];
            } else {
                int kk = e & 7, mm = e >> 3;
                As[kk][mm] = Ab[(size_t)(m0 + mm) * lda + k0 + kk];
            }
        }
        #pragma unroll
        for (int i = 0; i < 4; i++) {
            int e = t + 256 * i;
            if (TB) {
                int kk = e & 7, nn = e >> 3;
                Bs[kk][nn] = Bb[(size_t)(n0 + nn) * ldb + k0 + kk];
            } else {
                int nn = e & 127, kk = e >> 7;
                Bs[kk][nn] = Bb[(size_t)(k0 + kk) * ldb + n0 + nn];
            }
        }
        __syncthreads();

        #pragma unroll
        for (int kk = 0; kk < BK; kk++) {
            float ra[8], rb[8];
            float4 a0 = *reinterpret_cast<const float4*>(&As[kk][tm]);
            float4 a1 = *reinterpret_cast<const float4*>(&As[kk][tm + 4]);
            float4 b0 = *reinterpret_cast<const float4*>(&Bs[kk][tn]);
            float4 b1 = *reinterpret_cast<const float4*>(&Bs[kk][tn + 4]);
            ra[0]=a0.x; ra[1]=a0.y; ra[2]=a0.z; ra[3]=a0.w;
            ra[4]=a1.x; ra[5]=a1.y; ra[6]=a1.z; ra[7]=a1.w;
            rb[0]=b0.x; rb[1]=b0.y; rb[2]=b0.z; rb[3]=b0.w;
            rb[4]=b1.x; rb[5]=b1.y; rb[6]=b1.z; rb[7]=b1.w;
            #pragma unroll
            for (int i = 0; i < 8; i++)
                #pragma unroll
                for (int j = 0; j < 8; j++)
                    acc[i][j] += ra[i] * rb[j];
        }
        __syncthreads();
    }

    #pragma unroll
    for (int i = 0; i < 8; i++) {
        const int m = m0 + tm + i;
        const float bi = bias ? bias[m] : 0.f;
        #pragma unroll
        for (int j = 0; j < 8; j++) {
            const int n = n0 + tn + j;
            float v = alpha * acc[i][j] + bi;
            if (resid) v += resid[(size_t)b * strideR + (size_t)m * ldc + n];
            Cb[(size_t)m * ldc + n] = v;
        }
    }
}

// -------- row softmax over length-1024 rows --------
__global__ void softmax_kernel(float* __restrict__ s) {
    float* p = s + (size_t)blockIdx.x * NTOK;
    const int t = threadIdx.x;
    float v[4];
    float mx = -1e30f;
    #pragma unroll
    for (int i = 0; i < 4; i++) { v[i] = p[t + 256 * i]; mx = fmaxf(mx, v[i]); }
    __shared__ float red[256];
    red[t] = mx; __syncthreads();
    for (int o = 128; o > 0; o >>= 1) {
        if (t < o) red[t] = fmaxf(red[t], red[t + o]);
        __syncthreads();
    }
    mx = red[0];
    __syncthreads();
    float sm = 0.f;
    #pragma unroll
    for (int i = 0; i < 4; i++) { v[i] = __expf(v[i] - mx); sm += v[i]; }
    red[t] = sm; __syncthreads();
    for (int o = 128; o > 0; o >>= 1) {
        if (t < o) red[t] += red[t + o];
        __syncthreads();
    }
    const float inv = 1.f / red[0];
    #pragma unroll
    for (int i = 0; i < 4; i++) p[t + 256 * i] = v[i] * inv;
}

extern "C" void kernel_launch(void* const* d_in, const int* in_sizes, int n_in,
                              void* d_out, int out_size) {
    (void)in_sizes; (void)n_in; (void)out_size;
    const float* x  = (const float*)d_in[0];
    const float* gw = (const float*)d_in[1];
    const float* gb = (const float*)d_in[2];
    const float* wq = (const float*)d_in[3];
    const float* bq = (const float*)d_in[4];
    const float* wk = (const float*)d_in[5];
    const float* bk = (const float*)d_in[6];
    const float* wv = (const float*)d_in[7];
    const float* bv = (const float*)d_in[8];
    const float* wp = (const float*)d_in[9];
    const float* bp = (const float*)d_in[10];
    float* out = (float*)d_out;

    float *h, *q, *k, *v, *s, *o;
    cudaGetSymbolAddress((void**)&h, g_h);
    cudaGetSymbolAddress((void**)&q, g_q);
    cudaGetSymbolAddress((void**)&k, g_k);
    cudaGetSymbolAddress((void**)&v, g_v);
    cudaGetSymbolAddress((void**)&s, g_s);
    cudaGetSymbolAddress((void**)&o, g_o);

    const long CN = (long)CH * NTOK;     // per-batch stride of [C,N] tensors
    const long SS = (long)NTOK * NTOK;   // per-batch stride of scores

    // 1) GroupNorm -> h [B, C, N]
    gn_kernel<<<BATCH * NGRP, 256>>>(x, gw, gb, h);

    // 2) Q/K/V = W[512,512] @ h[512,1024] per batch (NN)
    dim3 gQKV(NTOK / 128, CH / 128, BATCH);   // (8,4,32)
    gemm_kernel<false, false><<<gQKV, 256>>>(wq, h, q, CH, NTOK, CH,
                                             CH, NTOK, NTOK, 0, CN, CN,
                                             1.f, bq, nullptr, 0);
    gemm_kernel<false, false><<<gQKV, 256>>>(wk, h, k, CH, NTOK, CH,
                                             CH, NTOK, NTOK, 0, CN, CN,
                                             1.f, bk, nullptr, 0);
    gemm_kernel<false, false><<<gQKV, 256>>>(wv, h, v, CH, NTOK, CH,
                                             CH, NTOK, NTOK, 0, CN, CN,
                                             1.f, bv, nullptr, 0);

    // 3) scores S[i,j] = scale * sum_c Q[c,i] K[c,j]   (TN)
    dim3 gS(NTOK / 128, NTOK / 128, BATCH);   // (8,8,32)
    const float scale = 1.0f / sqrtf((float)CH);
    gemm_kernel<true, false><<<gS, 256>>>(q, k, s, NTOK, NTOK, CH,
                                          NTOK, NTOK, NTOK, CN, CN, SS,
                                          scale, nullptr, nullptr, 0);

    // 4) softmax rows
    softmax_kernel<<<BATCH * NTOK, 256>>>(s);

    // 5) O[c,i] = sum_j V[c,j] P[i,j]   (NT)
    gemm_kernel<false, true><<<gQKV, 256>>>(v, s, o, CH, NTOK, NTOK,
                                            NTOK, NTOK, NTOK, CN, SS, CN,
                                            1.f, nullptr, nullptr, 0);

    // 6) out = x + wp @ O + bp   (NN, fused residual)
    gemm_kernel<false, false><<<gQKV, 256>>>(wp, o, out, CH, NTOK, CH,
                                             CH, NTOK, NTOK, 0, CN, CN,
                                             1.f, bp, x, CN);
}

// round 4
// speedup vs baseline: 6.3203x; 6.3203x over previous
#include <cuda_runtime.h>
#include <cuda_bf16.h>
#include <stdint.h>
#include <math.h>

#define BATCH 32
#define CH    512
#define NTOK  1024
#define NGRP  32
#define CPG   16

typedef __nv_bfloat16 bf16;
typedef unsigned int u32;

// ---------------- scratch (device globals) ----------------
__device__ bf16  g_h [(size_t)BATCH * NTOK * CH];   // [b][t][c]
__device__ bf16  g_q [(size_t)BATCH * NTOK * CH];   // [b][t][c]
__device__ bf16  g_k [(size_t)BATCH * NTOK * CH];   // [b][t][c]
__device__ bf16  g_vt[(size_t)BATCH * CH * NTOK];   // [b][c][t]
__device__ float g_s [(size_t)BATCH * NTOK * NTOK]; // scores fp32
__device__ bf16  g_p [(size_t)BATCH * NTOK * NTOK]; // probs bf16
__device__ bf16  g_o [(size_t)BATCH * NTOK * CH];   // [b][t][c]
__device__ bf16  g_w [4 * CH * CH];                 // wq|wk|wv|wp in bf16

// ---------------- weight fp32 -> bf16 ----------------
__global__ void convw_kernel(const float* __restrict__ wq, const float* __restrict__ wk,
                             const float* __restrict__ wv, const float* __restrict__ wp,
                             bf16* __restrict__ w) {
    int i = blockIdx.x * 256 + threadIdx.x;
    if (i < CH * CH) {
        w[i]               = __float2bfloat16(wq[i]);
        w[CH * CH + i]     = __float2bfloat16(wk[i]);
        w[2 * CH * CH + i] = __float2bfloat16(wv[i]);
        w[3 * CH * CH + i] = __float2bfloat16(wp[i]);
    }
}

// ---------------- GroupNorm: fp32 stats, bf16 token-major output ----------------
__global__ void gn_kernel(const float* __restrict__ x,
                          const float* __restrict__ gw,
                          const float* __restrict__ gb,
                          bf16* __restrict__ h) {
    const int bg = blockIdx.x;          // b*NGRP + g
    const int b = bg / NGRP, g = bg % NGRP;
    const int n = CPG * NTOK;
    const size_t base = (size_t)bg * n; // x offset for this (b,g)
    const int t = threadIdx.x;

    float s = 0.f, ss = 0.f;
    for (int i = t; i < n; i += 256) {
        float v = x[base + i];
        s += v; ss += v * v;
    }
    __shared__ float rs[256], rq[256];
    rs[t] = s; rq[t] = ss;
    __syncthreads();
    for (int o = 128; o > 0; o >>= 1) {
        if (t < o) { rs[t] += rs[t + o]; rq[t] += rq[t + o]; }
        __syncthreads();
    }
    const float mean = rs[0] * (1.0f / n);
    const float var  = rq[0] * (1.0f / n) - mean * mean;
    const float rstd = rsqrtf(var + 1e-5f);

    float a[CPG], c[CPG];
    #pragma unroll
    for (int i = 0; i < CPG; i++) {
        a[i] = rstd * gw[g * CPG + i];
        c[i] = gb[g * CPG + i] - mean * a[i];
    }

    for (int tok = t; tok < NTOK; tok += 256) {
        bf16 buf[CPG];
        #pragma unroll
        for (int i = 0; i < CPG; i++)
            buf[i] = __float2bfloat16(x[base + (size_t)i * NTOK + tok] * a[i] + c[i]);
        size_t ho = ((size_t)(b * NTOK + tok)) * CH + g * CPG;  // 16-elem aligned
        uint4* dst = reinterpret_cast<uint4*>(&h[ho]);
        const uint4* src = reinterpret_cast<const uint4*>(buf);
        dst[0] = src[0];
        dst[1] = src[1];
    }
}

// ---------------- epilogue store helpers ----------------
__device__ __forceinline__ void store2(float* p, float v0, float v1) {
    *reinterpret_cast<float2*>(p) = make_float2(v0, v1);
}
__device__ __forceinline__ void store2(bf16* p, float v0, float v1) {
    *reinterpret_cast<__nv_bfloat162*>(p) = __floats2bfloat162_rn(v0, v1);
}

// ---------------- bf16 TN GEMM via mma.sync.m16n8k16 ----------------
// C[m][n] = alpha * sum_k A[m][k]*B[n][k]  (+bias_m[m]) (+bias_n[n]) (+resid)
// A: [M][K] row-major (ld=K), B: [N][K] row-major (ld=K), C: [M][N] (ld=N).
#define BM 128
#define BN 128
#define BK 32
#define LDSW 40  // BK + 8 pad (conflict-free ldmatrix)

template<typename OutT>
__global__ void __launch_bounds__(256, 2)
mma_gemm(const bf16* __restrict__ A, const bf16* __restrict__ B, OutT* __restrict__ C,
         int K, int N, long sA, long sB, long sC,
         float alpha, const float* __restrict__ bias_m, const float* __restrict__ bias_n,
         const float* __restrict__ resid, long sR) {
    __shared__ bf16 As[2][BM * LDSW];
    __shared__ bf16 Bs[2][BN * LDSW];

    const int bz = blockIdx.z;
    const bf16* Ab = A + (size_t)bz * sA + (size_t)(blockIdx.y * BM) * K;
    const bf16* Bb = B + (size_t)bz * sB + (size_t)(blockIdx.x * BN) * K;

    const int t = threadIdx.x;
    const int lane = t & 31, w = t >> 5;
    const int wm = (w >> 2) * 64, wn = (w & 3) * 32;

    const int lr = t >> 2;          // load row (0..63)
    const int lc = (t & 3) * 8;     // load col (elems, 16B chunks)

    float acc[4][4][4] = {};

    // --- async tile loader ---
    auto issue = [&](int st, int k0) {
        #pragma unroll
        for (int i = 0; i < 2; i++) {
            int r = lr + i * 64;
            u32 da = (u32)__cvta_generic_to_shared(&As[st][r * LDSW + lc]);
            const bf16* ga = Ab + (size_t)r * K + k0 + lc;
            asm volatile("cp.async.cg.shared.global [%0], [%1], 16;\n" :: "r"(da), "l"(ga));
            u32 db = (u32)__cvta_generic_to_shared(&Bs[st][r * LDSW + lc]);
            const bf16* gbp = Bb + (size_t)r * K + k0 + lc;
            asm volatile("cp.async.cg.shared.global [%0], [%1], 16;\n" :: "r"(db), "l"(gbp));
        }
        asm volatile("cp.async.commit_group;\n");
    };

    issue(0, 0);
    const int KT = K / BK;
    for (int kt = 0; kt < KT; kt++) {
        asm volatile("cp.async.wait_group 0;\n");
        __syncthreads();
        if (kt + 1 < KT) issue((kt + 1) & 1, (kt + 1) * BK);
        const bf16* as = As[kt & 1];
        const bf16* bs = Bs[kt & 1];

        #pragma unroll
        for (int ks = 0; ks < 2; ks++) {
            u32 afrag[4][4], bfrag[4][2];
            #pragma unroll
            for (int mt = 0; mt < 4; mt++) {
                int row = wm + mt * 16 + (lane & 15);
                int col = ks * 16 + (lane >> 4) * 8;
                u32 addr = (u32)__cvta_generic_to_shared(&as[row * LDSW + col]);
                asm volatile("ldmatrix.sync.aligned.m8n8.x4.shared.b16 {%0,%1,%2,%3}, [%4];\n"
                    : "=r"(afrag[mt][0]), "=r"(afrag[mt][1]),
                      "=r"(afrag[mt][2]), "=r"(afrag[mt][3])
                    : "r"(addr));
            }
            #pragma unroll
            for (int np = 0; np < 2; np++) {
                int row = wn + np * 16 + (lane & 7) + ((lane >> 4) << 3);
                int col = ks * 16 + ((lane >> 3) & 1) * 8;
                u32 addr = (u32)__cvta_generic_to_shared(&bs[row * LDSW + col]);
                u32 bt0, bt1, bt2, bt3;
                asm volatile("ldmatrix.sync.aligned.m8n8.x4.shared.b16 {%0,%1,%2,%3}, [%4];\n"
                    : "=r"(bt0), "=r"(bt1), "=r"(bt2), "=r"(bt3) : "r"(addr));
                bfrag[np * 2][0]     = bt0;
                bfrag[np * 2][1]     = bt1;
                bfrag[np * 2 + 1][0] = bt2;
                bfrag[np * 2 + 1][1] = bt3;
            }
            #pragma unroll
            for (int mt = 0; mt < 4; mt++)
                #pragma unroll
                for (int nt = 0; nt < 4; nt++)
                    asm volatile(
                        "mma.sync.aligned.m16n8k16.row.col.f32.bf16.bf16.f32 "
                        "{%0,%1,%2,%3}, {%4,%5,%6,%7}, {%8,%9}, {%0,%1,%2,%3};\n"
                        : "+f"(acc[mt][nt][0]), "+f"(acc[mt][nt][1]),
                          "+f"(acc[mt][nt][2]), "+f"(acc[mt][nt][3])
                        : "r"(afrag[mt][0]), "r"(afrag[mt][1]),
                          "r"(afrag[mt][2]), "r"(afrag[mt][3]),
                          "r"(bfrag[nt][0]), "r"(bfrag[nt][1]));
        }
        __syncthreads();
    }

    // --- epilogue ---
    const int m0 = blockIdx.y * BM + wm, n0 = blockIdx.x * BN + wn;
    OutT* Cb = C + (size_t)bz * sC;
    const float* Rb = resid ? resid + (size_t)bz * sR : nullptr;
    #pragma unroll
    for (int mt = 0; mt < 4; mt++) {
        #pragma unroll
        for (int hh = 0; hh < 2; hh++) {
            int m = m0 + mt * 16 + (lane >> 2) + hh * 8;
            float bm = bias_m ? bias_m[m] : 0.f;
            #pragma unroll
            for (int nt = 0; nt < 4; nt++) {
                int n = n0 + nt * 8 + (lane & 3) * 2;
                float v0 = alpha * acc[mt][nt][hh * 2 + 0] + bm;
                float v1 = alpha * acc[mt][nt][hh * 2 + 1] + bm;
                if (bias_n) { v0 += bias_n[n]; v1 += bias_n[n + 1]; }
                size_t idx = (size_t)m * N + n;
                if (Rb) { v0 += Rb[idx]; v1 += Rb[idx + 1]; }
                store2(&Cb[idx], v0, v1);
            }
        }
    }
}

// ---------------- row softmax: fp32 in, bf16 out ----------------
__global__ void softmax_kernel(const float* __restrict__ s, bf16* __restrict__ p) {
    const float* sp = s + (size_t)blockIdx.x * NTOK;
    bf16* pp = p + (size_t)blockIdx.x * NTOK;
    const int t = threadIdx.x;
    float v[4];
    float mx = -1e30f;
    #pragma unroll
    for (int i = 0; i < 4; i++) { v[i] = sp[t + 256 * i]; mx = fmaxf(mx, v[i]); }
    __shared__ float red[256];
    red[t] = mx; __syncthreads();
    for (int o = 128; o > 0; o >>= 1) {
        if (t < o) red[t] = fmaxf(red[t], red[t + o]);
        __syncthreads();
    }
    mx = red[0];
    __syncthreads();
    float sm = 0.f;
    #pragma unroll
    for (int i = 0; i < 4; i++) { v[i] = __expf(v[i] - mx); sm += v[i]; }
    red[t] = sm; __syncthreads();
    for (int o = 128; o > 0; o >>= 1) {
        if (t < o) red[t] += red[t + o];
        __syncthreads();
    }
    const float inv = 1.f / red[0];
    #pragma unroll
    for (int i = 0; i < 4; i++) pp[t + 256 * i] = __float2bfloat16(v[i] * inv);
}

extern "C" void kernel_launch(void* const* d_in, const int* in_sizes, int n_in,
                              void* d_out, int out_size) {
    (void)in_sizes; (void)n_in; (void)out_size;
    const float* x  = (const float*)d_in[0];
    const float* gw = (const float*)d_in[1];
    const float* gb = (const float*)d_in[2];
    const float* wq = (const float*)d_in[3];
    const float* bq = (const float*)d_in[4];
    const float* wk = (const float*)d_in[5];
    const float* bk = (const float*)d_in[6];
    const float* wv = (const float*)d_in[7];
    const float* bv = (const float*)d_in[8];
    const float* wp = (const float*)d_in[9];
    const float* bp = (const float*)d_in[10];
    float* out = (float*)d_out;

    bf16 *h, *q, *k, *vt, *p, *o, *w;
    float *s;
    cudaGetSymbolAddress((void**)&h,  g_h);
    cudaGetSymbolAddress((void**)&q,  g_q);
    cudaGetSymbolAddress((void**)&k,  g_k);
    cudaGetSymbolAddress((void**)&vt, g_vt);
    cudaGetSymbolAddress((void**)&s,  g_s);
    cudaGetSymbolAddress((void**)&p,  g_p);
    cudaGetSymbolAddress((void**)&o,  g_o);
    cudaGetSymbolAddress((void**)&w,  g_w);

    const long NC = (long)NTOK * CH;   // per-batch activation stride
    const long SS = (long)NTOK * NTOK;

    convw_kernel<<<(CH * CH + 255) / 256, 256>>>(wq, wk, wv, wp, w);
    gn_kernel<<<BATCH * NGRP, 256>>>(x, gw, gb, h);

    // q[t][co] = h[t][:] . wq[co][:]   (bias on n)
    dim3 gQ(CH / BN, NTOK / BM, BATCH);       // (4,8,32)
    mma_gemm<bf16><<<gQ, 256>>>(h, w,               q, CH, CH, NC, 0, NC,
                                1.f, nullptr, bq, nullptr, 0);
    mma_gemm<bf16><<<gQ, 256>>>(h, w + CH * CH,     k, CH, CH, NC, 0, NC,
                                1.f, nullptr, bk, nullptr, 0);
    // vt[co][t] = wv[co][:] . h[t][:]  (bias on m)
    dim3 gV(NTOK / BN, CH / BM, BATCH);       // (8,4,32)
    mma_gemm<bf16><<<gV, 256>>>(w + 2 * CH * CH, h, vt, CH, NTOK, 0, NC, NC,
                                1.f, bv, nullptr, nullptr, 0);

    // scores S[tq][tk] = scale * q . k
    dim3 gS(NTOK / BN, NTOK / BM, BATCH);     // (8,8,32)
    const float scale = 1.0f / sqrtf((float)CH);
    mma_gemm<float><<<gS, 256>>>(q, k, s, CH, NTOK, NC, NC, SS,
                                 scale, nullptr, nullptr, nullptr, 0);

    softmax_kernel<<<BATCH * NTOK, 256>>>(s, p);

    // o[tq][c] = P[tq][:] . vt[c][:]
    dim3 gO(CH / BN, NTOK / BM, BATCH);       // (4,8,32)
    mma_gemm<bf16><<<gO, 256>>>(p, vt, o, NTOK, CH, SS, NC, NC,
                                1.f, nullptr, nullptr, nullptr, 0);

    // out[co][t] = x + wp[co][:] . o[t][:] + bp[co]
    dim3 gP(NTOK / BN, CH / BM, BATCH);       // (8,4,32)
    mma_gemm<float><<<gP, 256>>>(w + 3 * CH * CH, o, out, CH, NTOK, 0, NC, NC,
                                 1.f, bp, nullptr, x, NC);
}